// round 5
// baseline (speedup 1.0000x reference)
#include <cuda_runtime.h>
#include <math.h>

// Problem constants
#define NBc   16
#define NAc   5
#define NKc   9
#define NCc   13
#define NHc   38
#define NWc   38
#define MAXTc 50
#define NPIX  (NHc*NWc)        // 1444
#define NANCH (NAc*NPIX)       // 7220
#define NTOTc (NBc*NANCH)      // 115520
#define CHPA  (2*NKc+1+NCc)    // 32
#define TROW  21

// k_main decomposition: 4 threads per cell
#define CPB   32                           // cells per block
#define BPB   ((NANCH + CPB - 1)/CPB)      // 226 blocks per batch
#define NBLK  (NBc*BPB)                    // 3616 blocks
#define TPB   128

// meta record: [0]=key bits, [1]=tconf, [2]=cls, [3]=pad,
//              [4..21]=(gx,gy)*9 pixels, [22..39]=(vx,vy)*9
#define MSTRIDE 40

#define SCX   (640.0f/38.0f)
#define SCY   (480.0f/38.0f)
#define DENOM9   57.50150489f
#define STHRESH  34.50090293f   // 0.6 * 9 * (e^2 - 1)

__device__ int   g_nv[NBc];
__device__ float g_metaf[NBc][MAXTc*MSTRIDE];
__device__ float g_part[NBLK][2];
__device__ int   g_cnt = 0;

__device__ __forceinline__ float sigf(float x) { return 1.0f / (1.0f + __expf(-x)); }

// ============================================================================
// Kernel 1: per-batch meta (16 blocks, one per batch)
// ============================================================================
__global__ void __launch_bounds__(128)
k_meta(const float* __restrict__ out,
       const float* __restrict__ tgt,
       const float* __restrict__ anc) {
    __shared__ float s_t[MAXTc*TROW];
    __shared__ int   s_nv;
    const int b   = blockIdx.x;
    const int tid = threadIdx.x;
    const int lane = tid & 31;

    for (int i = tid; i < MAXTc*TROW; i += 128)
        s_t[i] = tgt[(size_t)b * (MAXTc*TROW) + i];
    __syncthreads();

    if (tid < 32) {
        unsigned m0 = __ballot_sync(0xFFFFFFFFu, s_t[lane*TROW + 1] != 0.0f);
        unsigned m1 = __ballot_sync(0xFFFFFFFFu,
                          (lane < MAXTc - 32) && (s_t[(lane+32)*TROW + 1] != 0.0f));
        if (lane == 0) {
            int nv;
            if (~m0) nv = __ffs(~m0) - 1;
            else {
                unsigned inv = (~m1) & ((1u << (MAXTc - 32)) - 1u);
                nv = inv ? 32 + __ffs(inv) - 1 : MAXTc;
            }
            s_nv = nv;
            g_nv[b] = nv;
        }
    }
    __syncthreads();
    const int nv = s_nv;

    if (tid < nv) {
        const int t = tid;
        const float* tb = &s_t[t*TROW];
        float* mr = &g_metaf[b][t*MSTRIDE];

        // best anchor by IoU (first-max)
        float gw = tb[19] * (float)NWc;
        float gh = tb[20] * (float)NHc;
        float best = -1.0f; int bn = 0;
        #pragma unroll
        for (int aa = 0; aa < NAc; ++aa) {
            float aw = anc[2*aa], ah = anc[2*aa+1];
            float cw = fminf(gw, aw), ch = fminf(gh, ah);
            float iou = 0.0f;
            if (cw > 0.0f && ch > 0.0f) {
                float ca = cw * ch;
                iou = ca / (gw * gh + aw * ah - ca);
            }
            if (iou > best) { best = iou; bn = aa; }
        }
        int gi0 = (int)floorf(tb[1] * (float)NWc);
        int gj0 = (int)floorf(tb[2] * (float)NHc);
        mr[0] = __int_as_float((bn << 12) | (gj0 << 6) | gi0);
        mr[2] = tb[0];
        mr[3] = 0.0f;

        float gxp[NKc], gyp[NKc];
        #pragma unroll
        for (int k = 0; k < NKc; ++k) {
            float gx = tb[1 + 2*k], gy = tb[2 + 2*k];
            gxp[k] = gx * 640.0f;  gyp[k] = gy * 480.0f;
            mr[4  + 2*k] = gxp[k];
            mr[5  + 2*k] = gyp[k];
            mr[22 + 2*k] = gx * (float)NWc - (float)gi0;
            mr[23 + 2*k] = gy * (float)NHc - (float)gj0;
        }

        // tconf at pidx-shifted cell
        long long p = (long long)b * NANCH - NPIX + (long long)gj0 * NWc + gi0;
        const long long tot = NTOTc;
        p = ((p % tot) + tot) % tot;
        int b2  = (int)(p / NANCH);
        int rem = (int)(p % NANCH);
        int a2  = rem / NPIX;
        int px2 = rem % NPIX;
        int h2 = px2 / NWc, w2 = px2 % NWc;
        const float* bo2 = out + ((size_t)(b2 * NAc + a2) * CHPA) * NPIX + px2;

        float s = 0.0f;
        #pragma unroll
        for (int k = 0; k < NKc; ++k) {
            float xv = bo2[(2*k)   * NPIX];
            float yv = bo2[(2*k+1) * NPIX];
            if (k == 0) { xv = sigf(xv); yv = sigf(yv); }
            float qx = (xv + (float)w2) * SCX;
            float qy = (yv + (float)h2) * SCY;
            float dx = gxp[k] - qx;
            float dy = gyp[k] - qy;
            float d2 = fmaf(dx, dx, dy * dy);
            if (d2 < 6400.0f) s += __expf(2.0f - sqrtf(d2) * 0.025f) - 1.0f;
        }
        mr[1] = s * (1.0f / DENOM9);
    }
}

// ============================================================================
// Kernel 2: per-cell loss, 4 threads per cell (targets split by t%4)
// ============================================================================
__global__ void __launch_bounds__(TPB, 10)
k_main(const float* __restrict__ out,
       const void*  __restrict__ epoch_ptr,
       float* __restrict__ d_out) {
    __shared__ float  s_meta[MAXTc*MSTRIDE];
    __shared__ int    s_nv;
    __shared__ float2 s_wred[TPB/32];
    __shared__ bool   s_last;

    const int tid   = threadIdx.x;
    const int lane  = tid & 31;
    const int wid   = tid >> 5;
    const int b     = blockIdx.x / BPB;
    const int ci    = tid >> 2;       // cell index within block (0..31)
    const int split = tid & 3;        // target-split (0..3)
    const int cell  = (blockIdx.x % BPB) * CPB + ci;
    const bool ok   = (cell < NANCH);

    // ---- per-cell channel loads (4 adjacent lanes hit same lines) ----------
    int a = 0, h = 0, w = 0;
    const float* baseo = out;
    float Px[NKc], Py[NKc], confv = 0.0f;
    if (ok) {
        a = cell / NPIX;
        int pix = cell % NPIX;
        h = pix / NWc; w = pix % NWc;
        baseo = out + ((size_t)(b * NAc + a) * CHPA) * NPIX + pix;
        float rc = baseo[(2*NKc) * NPIX];
        #pragma unroll
        for (int k = 0; k < NKc; ++k) {
            float xv = baseo[(2*k)   * NPIX];
            float yv = baseo[(2*k+1) * NPIX];
            if (k == 0) { xv = sigf(xv); yv = sigf(yv); }
            Px[k] = (xv + (float)w) * SCX;
            Py[k] = (yv + (float)h) * SCY;
        }
        confv = sigf(rc);
    }

    // ---- copy precomputed meta: fast path first 8 targets ------------------
    if (tid == 0) s_nv = g_nv[b];
    const float* mb = g_metaf[b];
    #pragma unroll
    for (int j = 0; j < (8*MSTRIDE + TPB - 1)/TPB; ++j) {
        int i = tid + j*TPB;
        if (i < 8*MSTRIDE) s_meta[i] = mb[i];
    }
    __syncthreads();
    const int nv = s_nv;
    if (nv > 8) {                     // generic fallback (not hit in this data)
        for (int i = 8*MSTRIDE + tid; i < nv*MSTRIDE; i += TPB) s_meta[i] = mb[i];
        __syncthreads();
    }

    // ---- match scan on this split's targets --------------------------------
    int m = -1;
    if (ok) {
        const int mykey = (a << 12) | (h << 6) | w;
        for (int t = split; t < nv; t += 4)
            if (__float_as_int(s_meta[t*MSTRIDE]) == mykey) m = t;
    }
    // combine match across the 4 split lanes (max index = last-write-wins)
    m = max(m, __shfl_xor_sync(0xFFFFFFFFu, m, 1));
    m = max(m, __shfl_xor_sync(0xFFFFFFFFu, m, 2));

    // ---- silence scan (only if unmatched) ----------------------------------
    int silent = 0;
    if (ok && m < 0) {
        for (int t = split; t < nv; t += 4) {
            const float2* gp = (const float2*)(s_meta + t*MSTRIDE + 4);
            float d2[NKc];
            #pragma unroll
            for (int k = 0; k < NKc; ++k) {
                float2 g = gp[k];
                float dx = Px[k] - g.x;
                float dy = Py[k] - g.y;
                d2[k] = fmaf(dx, dx, dy * dy);
            }
            float m01 = fminf(d2[0], d2[1]), m23 = fminf(d2[2], d2[3]);
            float m45 = fminf(d2[4], d2[5]), m67 = fminf(d2[6], d2[7]);
            float dmin = fminf(fminf(fminf(m01, m23), fminf(m45, m67)), d2[8]);
            if (dmin < 6400.0f) {
                float ssum = 0.0f;
                #pragma unroll
                for (int k = 0; k < NKc; ++k)
                    if (d2[k] < 6400.0f)
                        ssum += __expf(2.0f - sqrtf(d2[k]) * 0.025f) - 1.0f;
                if (ssum > STHRESH) { silent = 1; break; }
            }
        }
    }
    silent |= __shfl_xor_sync(0xFFFFFFFFu, silent, 1);
    silent |= __shfl_xor_sync(0xFFFFFFFFu, silent, 2);

    // ---- loss terms (split 0 of each cell only) ----------------------------
    float baseLoss = 0.0f, confLoss = 0.0f;
    if (ok && split == 0) {
        if (m >= 0) {
            const float* mr = &s_meta[m*MSTRIDE];
            // coord loss (reload raw channels; L1 hits)
            #pragma unroll
            for (int k = 0; k < NKc; ++k) {
                float xv = baseo[(2*k)   * NPIX];
                float yv = baseo[(2*k+1) * NPIX];
                if (k == 0) { xv = sigf(xv); yv = sigf(yv); }
                float dx = xv - mr[22 + 2*k];
                float dy = yv - mr[23 + 2*k];
                baseLoss += 0.5f * (dx*dx + dy*dy);
            }
            // class CE: two passes, no register array
            float mx = -1e30f;
            #pragma unroll
            for (int c = 0; c < NCc; ++c)
                mx = fmaxf(mx, baseo[(2*NKc + 1 + c) * NPIX]);
            float se = 0.0f;
            #pragma unroll
            for (int c = 0; c < NCc; ++c)
                se += __expf(baseo[(2*NKc + 1 + c) * NPIX] - mx);
            int lab = (int)mr[2];
            lab = lab < 0 ? 0 : (lab > NCc - 1 ? NCc - 1 : lab);
            baseLoss += __logf(se) + mx - baseo[(2*NKc + 1 + lab) * NPIX];
            float dc = confv - mr[1];
            confLoss = 2.5f * dc * dc;
        } else if (!silent) {
            confLoss = 0.5f * confv * confv;
        }
    }

    // ---- block reduction ----------------------------------------------------
    float v0 = baseLoss, v1 = confLoss;
    #pragma unroll
    for (int o = 16; o > 0; o >>= 1) {
        v0 += __shfl_down_sync(0xFFFFFFFFu, v0, o);
        v1 += __shfl_down_sync(0xFFFFFFFFu, v1, o);
    }
    if (lane == 0) s_wred[wid] = make_float2(v0, v1);
    __syncthreads();
    if (tid == 0) {
        float rb = s_wred[0].x + s_wred[1].x + s_wred[2].x + s_wred[3].x;
        float rc = s_wred[0].y + s_wred[1].y + s_wred[2].y + s_wred[3].y;
        g_part[blockIdx.x][0] = rb;
        g_part[blockIdx.x][1] = rc;
    }

    // ---- last-block-done final reduction ------------------------------------
    __threadfence();
    if (tid == 0) {
        int old = atomicAdd(&g_cnt, 1);
        s_last = (old == NBLK - 1);
    }
    __syncthreads();
    if (!s_last) return;

    float rb = 0.0f, rc = 0.0f;
    for (int idx = tid; idx < NBLK; idx += TPB) {
        rb += g_part[idx][0];
        rc += g_part[idx][1];
    }
    #pragma unroll
    for (int o = 16; o > 0; o >>= 1) {
        rb += __shfl_down_sync(0xFFFFFFFFu, rb, o);
        rc += __shfl_down_sync(0xFFFFFFFFu, rc, o);
    }
    if (lane == 0) s_wred[wid] = make_float2(rb, rc);
    __syncthreads();
    if (tid == 0) {
        float tb2 = s_wred[0].x + s_wred[1].x + s_wred[2].x + s_wred[3].x;
        float tc2 = s_wred[0].y + s_wred[1].y + s_wred[2].y + s_wred[3].y;
        int ev = ((const int*)epoch_ptr)[0];
        if (ev > 1000000 || ev < -1000000) ev = (int)__int_as_float(ev);
        float total = tb2;
        if (ev > 15) total += tc2;
        d_out[0] = total;
        g_cnt = 0;   // reset for graph replay
    }
}

extern "C" void kernel_launch(void* const* d_in, const int* in_sizes, int n_in,
                              void* d_out, int out_size) {
    const float* out_t = (const float*)d_in[0];
    const float* tgt   = (const float*)d_in[1];
    const float* anc   = (const float*)d_in[2];
    const void*  epoch = d_in[3];
    k_meta<<<NBc, 128>>>(out_t, tgt, anc);
    k_main<<<NBLK, TPB>>>(out_t, epoch, (float*)d_out);
}